// round 3
// baseline (speedup 1.0000x reference)
#include <cuda_runtime.h>
#include <math.h>

#define BB 8
#define HH 1024
#define LL 2048
#define NN 64
#define NF 4096
#define PADI(i) ((i) + ((i) >> 4))
#define BUFSZ 4352

// ---------------- device scratch (no allocation) ----------------
__device__ float2 g_cden[LL * NN];          // 1 MB
__device__ float2 g_fl[LL];
__device__ float2 g_cl[LL];
__device__ float2 g_ar[(size_t)HH * LL];    // 16 MB
__device__ float2 g_Kf[(size_t)HH * NF];    // 32 MB
__device__ float2 g_tw[1025];               // exp(-2pi i j/4096), j=0..1024

// ---------------- complex helpers ----------------
__device__ __forceinline__ float2 cmulf(float2 a, float2 b) {
    return make_float2(fmaf(a.x, b.x, -a.y * b.y), fmaf(a.x, b.y, a.y * b.x));
}
__device__ __forceinline__ void cfma(float2& acc, float2 a, float2 b) {
    acc.x = fmaf(a.x, b.x, fmaf(-a.y, b.y, acc.x));
    acc.y = fmaf(a.x, b.y, fmaf(a.y, b.x, acc.y));
}
__device__ __forceinline__ float2 cadd(float2 a, float2 b) { return make_float2(a.x + b.x, a.y + b.y); }
__device__ __forceinline__ float2 csub(float2 a, float2 b) { return make_float2(a.x - b.x, a.y - b.y); }

// ---------------- K0: twiddle table ----------------
__global__ void k_tw() {
    int j = blockIdx.x * blockDim.x + threadIdx.x;
    if (j > 1024) return;
    float ang = -6.28318530717958647692f * (float)j / (float)NF;
    float s, c;
    sincosf(ang, &s, &c);
    g_tw[j] = make_float2(c, s);
}

// ---------------- K1: per-frequency prep ----------------
__global__ void k_prep(const float* __restrict__ B_re, const float* __restrict__ B_im,
                       const float* __restrict__ P_re, const float* __restrict__ P_im,
                       const float* __restrict__ Q_re, const float* __restrict__ Q_im,
                       const float* __restrict__ dre,  const float* __restrict__ dim_,
                       const float* __restrict__ step) {
    int l = blockIdx.x * blockDim.x + threadIdx.x;
    if (l >= LL) return;
    float st = fmaxf(step[0], 1e-6f);
    float ang = (-6.28318530717958647692f * (float)l) / (float)LL;
    float zs, zc;
    sincosf(ang, &zs, &zc);
    float2 omz = make_float2(1.0f - zc, -zs);   // 1 - z
    float2 opz = make_float2(1.0f + zc, zs);    // 1 + z
    float invp = 1.0f / (opz.x * opz.x + opz.y * opz.y);
    float2 q = cmulf(omz, make_float2(opz.x, -opz.y));
    float2 g = make_float2((2.0f / st) * q.x * invp, (2.0f / st) * q.y * invp);
    float2 k10 = make_float2(0.f, 0.f), k11 = make_float2(0.f, 0.f);
    for (int n = 0; n < NN; n++) {
        float2 den = make_float2(g.x - dre[n], g.y - dim_[n]);
        float di = 1.0f / (den.x * den.x + den.y * den.y);
        float2 cd = make_float2(den.x * di, -den.y * di);  // 1/(g - Lam)
        g_cden[(size_t)l * NN + n] = cd;
        float2 Bv = make_float2(B_re[n], B_im[n]);
        float2 Pv = make_float2(P_re[n], P_im[n]);
        float2 Qv = make_float2(Q_re[n], Q_im[n]);
        cfma(k10, cmulf(Qv, Bv), cd);
        cfma(k11, cmulf(Qv, Pv), cd);
    }
    float2 onep = make_float2(1.0f + k11.x, k11.y);
    float i2 = 1.0f / (onep.x * onep.x + onep.y * onep.y);
    float2 c = cmulf(k10, make_float2(onep.x * i2, -onep.y * i2));
    g_fl[l] = make_float2(2.0f * opz.x * invp, -2.0f * opz.y * invp);  // 2/(1+z)
    g_cl[l] = c;
}

// ---------------- K2: at_roots = f*(k00 - c*k01) ----------------
// grid (L/64, H/128), 256 threads. Shared: cden tile [64 l][64 n], CB/CP [8 h][64 n].
__global__ void __launch_bounds__(256) k_ar(const float* __restrict__ C_re, const float* __restrict__ C_im,
                                            const float* __restrict__ B_re, const float* __restrict__ B_im,
                                            const float* __restrict__ P_re, const float* __restrict__ P_im) {
    __shared__ float2 sCD[64 * 65];
    __shared__ float2 sCB[8 * 65];
    __shared__ float2 sCP[8 * 65];
    int l0 = blockIdx.x * 64;
    int tid = threadIdx.x;
    for (int i = tid; i < 64 * 64; i += 256) {
        int ll = i >> 6, n = i & 63;
        sCD[ll * 65 + n] = g_cden[(size_t)(l0 + ll) * NN + n];
    }
    int th = tid >> 5;       // 0..7 (h within chunk)
    int tl = tid & 31;       // 0..31 (l thread)
    for (int hc = 0; hc < 16; hc++) {
        int hb = blockIdx.y * 128 + hc * 8;
        __syncthreads();
        for (int i = tid; i < 8 * 64; i += 256) {
            int hh = i >> 6, n = i & 63;
            float2 Cv = make_float2(C_re[(size_t)(hb + hh) * NN + n], C_im[(size_t)(hb + hh) * NN + n]);
            sCB[hh * 65 + n] = cmulf(Cv, make_float2(B_re[n], B_im[n]));
            sCP[hh * 65 + n] = cmulf(Cv, make_float2(P_re[n], P_im[n]));
        }
        __syncthreads();
        float2 a00a = make_float2(0.f, 0.f), a01a = make_float2(0.f, 0.f);
        float2 a00b = make_float2(0.f, 0.f), a01b = make_float2(0.f, 0.f);
#pragma unroll
        for (int n = 0; n < 64; n++) {
            float2 cb = sCB[th * 65 + n];
            float2 cp = sCP[th * 65 + n];
            float2 c0 = sCD[tl * 65 + n];
            float2 c1 = sCD[(tl + 32) * 65 + n];
            cfma(a00a, cb, c0); cfma(a01a, cp, c0);
            cfma(a00b, cb, c1); cfma(a01b, cp, c1);
        }
        int h = hb + th;
        int la = l0 + tl, lb = la + 32;
        float2 fa = g_fl[la], ca = g_cl[la];
        float2 fb = g_fl[lb], cb2 = g_cl[lb];
        g_ar[(size_t)h * LL + la] = cmulf(fa, csub(a00a, cmulf(ca, a01a)));
        g_ar[(size_t)h * LL + lb] = cmulf(fb, csub(a00b, cmulf(cb2, a01b)));
    }
}

// ---------------- block FFT: radix-4 Stockham, 256 threads ----------------
// DIR=-1 forward, DIR=+1 inverse (unscaled). Result lands in x. Caller syncs before.
template <int NFFT, int DIR>
__device__ __forceinline__ void block_fft(float2* x, float2* y, const float2* __restrict__ tw) {
    float2* src = x;
    float2* dst = y;
    int nn = NFFT, ls = 0;
    while (nn > 2) {
        int tstep = NF / nn;
        for (int idx = threadIdx.x; idx < (NFFT >> 2); idx += 256) {
            int p = idx >> ls;
            int q = idx & ((1 << ls) - 1);
            int base = q + (p << ls);
            float2 a = src[PADI(base)];
            float2 b = src[PADI(base + (NFFT >> 2))];
            float2 c = src[PADI(base + (NFFT >> 1))];
            float2 d = src[PADI(base + 3 * (NFFT >> 2))];
            float2 apc = cadd(a, c), amc = csub(a, c);
            float2 bpd = cadd(b, d), bmd = csub(b, d);
            float2 u0 = cadd(apc, bpd);
            float2 u2 = csub(apc, bpd);
            float2 jb = make_float2(-(float)DIR * bmd.y, (float)DIR * bmd.x);  // DIR*i*bmd
            float2 u1 = cadd(amc, jb);
            float2 u3 = csub(amc, jb);
            float2 w1 = tw[p * tstep];
            if (DIR > 0) w1.y = -w1.y;
            float2 w2 = cmulf(w1, w1);
            float2 w3 = cmulf(w2, w1);
            int ob = q + (p << (ls + 2));
            dst[PADI(ob)] = u0;
            dst[PADI(ob + (1 << ls))] = cmulf(u1, w1);
            dst[PADI(ob + (2 << ls))] = cmulf(u2, w2);
            dst[PADI(ob + (3 << ls))] = cmulf(u3, w3);
        }
        __syncthreads();
        float2* t = src; src = dst; dst = t;
        nn >>= 2;
        ls += 2;
    }
    if (nn == 2) {  // final radix-2 (NFFT=2048 path)
        for (int idx = threadIdx.x; idx < (NFFT >> 1); idx += 256) {
            float2 a = src[PADI(idx)];
            float2 b = src[PADI(idx + (NFFT >> 1))];
            dst[PADI(idx)] = cadd(a, b);
            dst[PADI(idx + (NFFT >> 1))] = csub(a, b);
        }
        __syncthreads();
    }
}

// ---------------- K3: kernel spectrum per channel ----------------
__global__ void __launch_bounds__(256) k_kf() {
    extern __shared__ float2 sh2[];
    float2* A = sh2;
    float2* Bb = sh2 + BUFSZ;
    __shared__ float2 stw[1025];
    int h = blockIdx.x;
    for (int j = threadIdx.x; j < 1025; j += 256) stw[j] = g_tw[j];
    for (int l = threadIdx.x; l < LL; l += 256) A[PADI(l)] = g_ar[(size_t)h * LL + l];
    __syncthreads();
    block_fft<LL, 1>(A, Bb, stw);   // unscaled inverse DFT, result in A
    float kv[8];
#pragma unroll
    for (int i = 0; i < 8; i++) {
        int l = threadIdx.x + i * 256;
        kv[i] = A[PADI(l)].x * (1.0f / (float)LL);  // ifft(..).real
    }
#pragma unroll
    for (int i = 0; i < 8; i++) {
        int l = threadIdx.x + i * 256;
        A[PADI(l)] = make_float2(kv[i], 0.f);
        A[PADI(l + LL)] = make_float2(0.f, 0.f);    // zero-pad to 4096
    }
    __syncthreads();
    block_fft<NF, -1>(A, Bb, stw);  // forward, result in A
    for (int k = threadIdx.x; k < NF; k += 256) g_Kf[(size_t)h * NF + k] = A[PADI(k)];
}

// ---------------- K4: FFT convolution, 2 channels per CTA ----------------
__global__ void __launch_bounds__(256) k_conv(const float* __restrict__ r, float* __restrict__ out,
                                              const float* __restrict__ Dp) {
    extern __shared__ float2 sh2[];
    float2* A = sh2;
    float2* Bb = sh2 + BUFSZ;
    __shared__ float2 stw[1025];
    int hp = blockIdx.x;          // channel pair 0..511
    int b = blockIdx.y;
    int h0 = hp * 2;
    float Dv = Dp[0];
    for (int j = threadIdx.x; j < 1025; j += 256) stw[j] = g_tw[j];
    const float2* rp = (const float2*)(r + (size_t)b * LL * HH);
    float2 rv[8];
#pragma unroll
    for (int i = 0; i < 8; i++) {
        int l = threadIdx.x + i * 256;
        rv[i] = rp[(size_t)l * (HH / 2) + hp];
        A[PADI(l)] = rv[i];
        A[PADI(l + LL)] = make_float2(0.f, 0.f);
    }
    __syncthreads();
    block_fft<NF, -1>(A, Bb, stw);  // U in A
    const float2* K0 = g_Kf + (size_t)h0 * NF;
    const float2* K1 = K0 + NF;
    for (int k = threadIdx.x; k <= NF / 2; k += 256) {
        int km = (NF - k) & (NF - 1);
        float2 a = A[PADI(k)];
        float2 bc = A[PADI(km)]; bc.y = -bc.y;          // conj(U[N-k])
        float2 X0 = make_float2(0.5f * (a.x + bc.x), 0.5f * (a.y + bc.y));
        float2 dd = make_float2(0.5f * (a.x - bc.x), 0.5f * (a.y - bc.y));
        float2 X1 = make_float2(dd.y, -dd.x);           // -i * dd
        float2 t0 = cmulf(X0, K0[k]);
        float2 t1 = cmulf(X1, K1[k]);
        // V[k] = t0 + i*t1 ; V[N-k] = conj(t0) + i*conj(t1)
        A[PADI(k)]  = make_float2(t0.x - t1.y, t0.y + t1.x);
        A[PADI(km)] = make_float2(t0.x + t1.y, -t0.y + t1.x);
    }
    __syncthreads();
    block_fft<NF, 1>(A, Bb, stw);   // unscaled inverse, result in A
    float2* op = (float2*)(out + (size_t)b * LL * HH);
#pragma unroll
    for (int i = 0; i < 8; i++) {
        int l = threadIdx.x + i * 256;
        float2 v = A[PADI(l)];
        float y0 = fmaf(Dv, rv[i].x, v.x * (1.0f / (float)NF));
        float y1 = fmaf(Dv, rv[i].y, v.y * (1.0f / (float)NF));
        float g0 = 0.5f * y0 * (1.0f + erff(y0 * 0.70710678118654752f));
        float g1 = 0.5f * y1 * (1.0f + erff(y1 * 0.70710678118654752f));
        op[(size_t)l * (HH / 2) + hp] = make_float2(g0, g1);
    }
}

// ---------------- launch ----------------
extern "C" void kernel_launch(void* const* d_in, const int* in_sizes, int n_in,
                              void* d_out, int out_size) {
    const float* r    = (const float*)d_in[0];
    const float* B_re = (const float*)d_in[1];
    const float* B_im = (const float*)d_in[2];
    const float* C_re = (const float*)d_in[3];
    const float* C_im = (const float*)d_in[4];
    const float* P_re = (const float*)d_in[5];
    const float* P_im = (const float*)d_in[6];
    const float* Q_re = (const float*)d_in[7];
    const float* Q_im = (const float*)d_in[8];
    const float* dre  = (const float*)d_in[9];
    const float* dim_ = (const float*)d_in[10];
    const float* step = (const float*)d_in[11];
    const float* Dp   = (const float*)d_in[12];
    float* out = (float*)d_out;

    static int attr_done = 0;
    if (!attr_done) {
        cudaFuncSetAttribute(k_kf,   cudaFuncAttributeMaxDynamicSharedMemorySize, 2 * BUFSZ * sizeof(float2));
        cudaFuncSetAttribute(k_conv, cudaFuncAttributeMaxDynamicSharedMemorySize, 2 * BUFSZ * sizeof(float2));
        attr_done = 1;
    }

    k_tw<<<5, 256>>>();
    k_prep<<<8, 256>>>(B_re, B_im, P_re, P_im, Q_re, Q_im, dre, dim_, step);
    k_ar<<<dim3(LL / 64, HH / 128), 256>>>(C_re, C_im, B_re, B_im, P_re, P_im);
    k_kf<<<HH, 256, 2 * BUFSZ * sizeof(float2)>>>();
    k_conv<<<dim3(HH / 2, BB), 256, 2 * BUFSZ * sizeof(float2)>>>(r, out, Dp);
}

// round 6
// speedup vs baseline: 1.8728x; 1.8728x over previous
#include <cuda_runtime.h>
#include <math.h>

#define BB 8
#define HH 1024
#define LL 2048
#define NN 64
#define NF 4096
#define PADI(i) ((i) + ((i) >> 4))
#define BUFSZ 4352

// ---------------- device scratch ----------------
__device__ float2 g_cden[LL * NN];
__device__ float2 g_fl[LL];
__device__ float2 g_cl[LL];
__device__ float2 g_ar[(size_t)HH * LL];    // 16 MB
__device__ float2 g_Kf[(size_t)HH * NF];    // 32 MB
__device__ float2 g_tw[1025];               // exp(-2pi i j/4096)

__device__ __forceinline__ float2 cmulf(float2 a, float2 b) {
    return make_float2(fmaf(a.x, b.x, -a.y * b.y), fmaf(a.x, b.y, a.y * b.x));
}
__device__ __forceinline__ void cfma(float2& acc, float2 a, float2 b) {
    acc.x = fmaf(a.x, b.x, fmaf(-a.y, b.y, acc.x));
    acc.y = fmaf(a.x, b.y, fmaf(a.y, b.x, acc.y));
}
__device__ __forceinline__ float2 cadd(float2 a, float2 b) { return make_float2(a.x + b.x, a.y + b.y); }
__device__ __forceinline__ float2 csub(float2 a, float2 b) { return make_float2(a.x - b.x, a.y - b.y); }

template <int DIR>
__device__ __forceinline__ void dft4v(float2 v[4]) {
    float2 apc = cadd(v[0], v[2]), amc = csub(v[0], v[2]);
    float2 bpd = cadd(v[1], v[3]), bmd = csub(v[1], v[3]);
    float2 jb = make_float2(-(float)DIR * bmd.y, (float)DIR * bmd.x);
    v[0] = cadd(apc, bpd); v[1] = cadd(amc, jb);
    v[2] = csub(apc, bpd); v[3] = csub(amc, jb);
}

// natural-order 8-point DFT, DIR=-1 fwd / +1 inv
template <int DIR>
__device__ __forceinline__ void dft8(float2 v[8]) {
    float2 e[4] = {v[0], v[2], v[4], v[6]};
    float2 o[4] = {v[1], v[3], v[5], v[7]};
    dft4v<DIR>(e);
    dft4v<DIR>(o);
    const float R2 = 0.70710678118654752440f;
    float2 w1 = make_float2(R2, (float)DIR * R2);
    float2 w3 = make_float2(-R2, (float)DIR * R2);
    float2 o1 = cmulf(o[1], w1);
    float2 o2 = make_float2(-(float)DIR * o[2].y, (float)DIR * o[2].x);
    float2 o3 = cmulf(o[3], w3);
    v[0] = cadd(e[0], o[0]); v[4] = csub(e[0], o[0]);
    v[1] = cadd(e[1], o1);   v[5] = csub(e[1], o1);
    v[2] = cadd(e[2], o2);   v[6] = csub(e[2], o2);
    v[3] = cadd(e[3], o3);   v[7] = csub(e[3], o3);
}

// ---------------- radix-8 Stockham block FFT, NT threads ----------------
// DIR=-1 forward, DIR=+1 inverse (unscaled). Result lands in x. Caller syncs before.
template <int NFFT, int DIR, int NT>
__device__ __forceinline__ void block_fft(float2* x, float2* y) {
    float2* src = x;
    float2* dst = y;
    int nn = NFFT, ls = 0;
    while (nn >= 8) {
        int tstep = NF / nn;
        for (int idx = threadIdx.x; idx < (NFFT >> 3); idx += NT) {
            int p = idx >> ls;
            int q = idx & ((1 << ls) - 1);
            int base = q + (p << ls);
            float2 v[8];
#pragma unroll
            for (int j = 0; j < 8; j++) v[j] = src[PADI(base + j * (NFFT >> 3))];
            dft8<DIR>(v);
            float2 w1 = __ldg(&g_tw[p * tstep]);
            if (DIR > 0) w1.y = -w1.y;
            int ob = q + (p << (ls + 3));
            dst[PADI(ob)] = v[0];
            float2 wk = w1;
            dst[PADI(ob + (1 << ls))] = cmulf(v[1], wk);
#pragma unroll
            for (int k = 2; k < 8; k++) {
                wk = cmulf(wk, w1);
                dst[PADI(ob + (k << ls))] = cmulf(v[k], wk);
            }
        }
        __syncthreads();
        float2* t = src; src = dst; dst = t;
        nn >>= 3;
        ls += 3;
    }
    if (nn == 4) {  // final twiddle-free radix-4 (2048 path); p==0 always
        for (int idx = threadIdx.x; idx < (NFFT >> 2); idx += NT) {
            float2 v[4];
#pragma unroll
            for (int j = 0; j < 4; j++) v[j] = src[PADI(idx + j * (NFFT >> 2))];
            dft4v<DIR>(v);
#pragma unroll
            for (int k = 0; k < 4; k++) dst[PADI(idx + (k << ls))] = v[k];
        }
        __syncthreads();
    }
    // NFFT=4096: 4 radix-8 passes -> result in x. NFFT=2048: 3 + radix4 -> x.
}

// ---------------- K0: twiddle table ----------------
__global__ void k_tw() {
    int j = blockIdx.x * blockDim.x + threadIdx.x;
    if (j > 1024) return;
    float ang = -6.28318530717958647692f * (float)j / (float)NF;
    float s, c;
    sincosf(ang, &s, &c);
    g_tw[j] = make_float2(c, s);
}

// ---------------- K1: per-frequency prep ----------------
__global__ void k_prep(const float* __restrict__ B_re, const float* __restrict__ B_im,
                       const float* __restrict__ P_re, const float* __restrict__ P_im,
                       const float* __restrict__ Q_re, const float* __restrict__ Q_im,
                       const float* __restrict__ dre,  const float* __restrict__ dim_,
                       const float* __restrict__ step) {
    int l = blockIdx.x * blockDim.x + threadIdx.x;
    if (l >= LL) return;
    float st = fmaxf(step[0], 1e-6f);
    float ang = (-6.28318530717958647692f * (float)l) / (float)LL;
    float zs, zc;
    sincosf(ang, &zs, &zc);
    float2 omz = make_float2(1.0f - zc, -zs);
    float2 opz = make_float2(1.0f + zc, zs);
    float invp = 1.0f / (opz.x * opz.x + opz.y * opz.y);
    float2 q = cmulf(omz, make_float2(opz.x, -opz.y));
    float2 g = make_float2((2.0f / st) * q.x * invp, (2.0f / st) * q.y * invp);
    float2 k10 = make_float2(0.f, 0.f), k11 = make_float2(0.f, 0.f);
    for (int n = 0; n < NN; n++) {
        float2 den = make_float2(g.x - dre[n], g.y - dim_[n]);
        float di = 1.0f / (den.x * den.x + den.y * den.y);
        float2 cd = make_float2(den.x * di, -den.y * di);
        g_cden[(size_t)l * NN + n] = cd;
        float2 Bv = make_float2(B_re[n], B_im[n]);
        float2 Pv = make_float2(P_re[n], P_im[n]);
        float2 Qv = make_float2(Q_re[n], Q_im[n]);
        cfma(k10, cmulf(Qv, Bv), cd);
        cfma(k11, cmulf(Qv, Pv), cd);
    }
    float2 onep = make_float2(1.0f + k11.x, k11.y);
    float i2 = 1.0f / (onep.x * onep.x + onep.y * onep.y);
    float2 c = cmulf(k10, make_float2(onep.x * i2, -onep.y * i2));
    g_fl[l] = make_float2(2.0f * opz.x * invp, -2.0f * opz.y * invp);
    g_cl[l] = c;
}

// ---------------- K2: at_roots = f*(k00 - c*k01) ----------------
__global__ void __launch_bounds__(256) k_ar(const float* __restrict__ C_re, const float* __restrict__ C_im,
                                            const float* __restrict__ B_re, const float* __restrict__ B_im,
                                            const float* __restrict__ P_re, const float* __restrict__ P_im) {
    __shared__ float2 sCD[64 * 65];
    __shared__ float2 sCB[8 * 65];
    __shared__ float2 sCP[8 * 65];
    int l0 = blockIdx.x * 64;
    int tid = threadIdx.x;
    for (int i = tid; i < 64 * 64; i += 256) {
        int ll = i >> 6, n = i & 63;
        sCD[ll * 65 + n] = g_cden[(size_t)(l0 + ll) * NN + n];
    }
    int th = tid >> 5;
    int tl = tid & 31;
    for (int hc = 0; hc < 16; hc++) {
        int hb = blockIdx.y * 128 + hc * 8;
        __syncthreads();
        for (int i = tid; i < 8 * 64; i += 256) {
            int hh = i >> 6, n = i & 63;
            float2 Cv = make_float2(C_re[(size_t)(hb + hh) * NN + n], C_im[(size_t)(hb + hh) * NN + n]);
            sCB[hh * 65 + n] = cmulf(Cv, make_float2(B_re[n], B_im[n]));
            sCP[hh * 65 + n] = cmulf(Cv, make_float2(P_re[n], P_im[n]));
        }
        __syncthreads();
        float2 a00a = make_float2(0.f, 0.f), a01a = make_float2(0.f, 0.f);
        float2 a00b = make_float2(0.f, 0.f), a01b = make_float2(0.f, 0.f);
#pragma unroll
        for (int n = 0; n < 64; n++) {
            float2 cb = sCB[th * 65 + n];
            float2 cp = sCP[th * 65 + n];
            float2 c0 = sCD[tl * 65 + n];
            float2 c1 = sCD[(tl + 32) * 65 + n];
            cfma(a00a, cb, c0); cfma(a01a, cp, c0);
            cfma(a00b, cb, c1); cfma(a01b, cp, c1);
        }
        int h = hb + th;
        int la = l0 + tl, lb = la + 32;
        float2 fa = g_fl[la], ca = g_cl[la];
        float2 fb = g_fl[lb], cb2 = g_cl[lb];
        g_ar[(size_t)h * LL + la] = cmulf(fa, csub(a00a, cmulf(ca, a01a)));
        g_ar[(size_t)h * LL + lb] = cmulf(fb, csub(a00b, cmulf(cb2, a01b)));
    }
}

// ---------------- K3: kernel spectrum per channel (512 threads) ----------------
__global__ void __launch_bounds__(512, 2) k_kf() {
    extern __shared__ float2 sh2[];
    float2* A = sh2;
    float2* Bb = sh2 + BUFSZ;
    int h = blockIdx.x;
    for (int l = threadIdx.x; l < LL; l += 512) A[PADI(l)] = g_ar[(size_t)h * LL + l];
    __syncthreads();
    block_fft<LL, 1, 512>(A, Bb);   // unscaled inverse DFT -> A
    float kv[4];
#pragma unroll
    for (int i = 0; i < 4; i++) {
        int l = threadIdx.x + i * 512;
        kv[i] = A[PADI(l)].x * (1.0f / (float)LL);
    }
    __syncthreads();
#pragma unroll
    for (int i = 0; i < 4; i++) {
        int l = threadIdx.x + i * 512;
        A[PADI(l)] = make_float2(kv[i], 0.f);
        A[PADI(l + LL)] = make_float2(0.f, 0.f);
    }
    __syncthreads();
    block_fft<NF, -1, 512>(A, Bb);  // forward -> A
    for (int k = threadIdx.x; k < NF; k += 512) g_Kf[(size_t)h * NF + k] = A[PADI(k)];
}

// ---------------- K4: FFT convolution, 2 channels per CTA (512 threads) ----------------
__global__ void __launch_bounds__(512, 2) k_conv(const float* __restrict__ r, float* __restrict__ out,
                                                 const float* __restrict__ Dp) {
    extern __shared__ float2 sh2[];
    float2* A = sh2;
    float2* Bb = sh2 + BUFSZ;
    int hp = blockIdx.x;
    int b = blockIdx.y;
    int h0 = hp * 2;
    float Dv = Dp[0];
    const float2* rp = (const float2*)(r + (size_t)b * LL * HH);
    float2 rv[4];
#pragma unroll
    for (int i = 0; i < 4; i++) {
        int l = threadIdx.x + i * 512;
        rv[i] = rp[(size_t)l * (HH / 2) + hp];
        A[PADI(l)] = rv[i];
        A[PADI(l + LL)] = make_float2(0.f, 0.f);
    }
    __syncthreads();
    block_fft<NF, -1, 512>(A, Bb);  // U -> A
    const float2* K0 = g_Kf + (size_t)h0 * NF;
    const float2* K1 = K0 + NF;
    for (int k = threadIdx.x; k <= NF / 2; k += 512) {
        int km = (NF - k) & (NF - 1);
        float2 a = A[PADI(k)];
        float2 bc = A[PADI(km)]; bc.y = -bc.y;
        float2 X0 = make_float2(0.5f * (a.x + bc.x), 0.5f * (a.y + bc.y));
        float2 dd = make_float2(0.5f * (a.x - bc.x), 0.5f * (a.y - bc.y));
        float2 X1 = make_float2(dd.y, -dd.x);
        float2 t0 = cmulf(X0, __ldg(&K0[k]));
        float2 t1 = cmulf(X1, __ldg(&K1[k]));
        A[PADI(k)]  = make_float2(t0.x - t1.y, t0.y + t1.x);
        A[PADI(km)] = make_float2(t0.x + t1.y, -t0.y + t1.x);
    }
    __syncthreads();
    block_fft<NF, 1, 512>(A, Bb);   // unscaled inverse -> A
    float2* op = (float2*)(out + (size_t)b * LL * HH);
#pragma unroll
    for (int i = 0; i < 4; i++) {
        int l = threadIdx.x + i * 512;
        float2 v = A[PADI(l)];
        float y0 = fmaf(Dv, rv[i].x, v.x * (1.0f / (float)NF));
        float y1 = fmaf(Dv, rv[i].y, v.y * (1.0f / (float)NF));
        float g0 = 0.5f * y0 * (1.0f + erff(y0 * 0.70710678118654752f));
        float g1 = 0.5f * y1 * (1.0f + erff(y1 * 0.70710678118654752f));
        op[(size_t)l * (HH / 2) + hp] = make_float2(g0, g1);
    }
}

// ---------------- launch ----------------
extern "C" void kernel_launch(void* const* d_in, const int* in_sizes, int n_in,
                              void* d_out, int out_size) {
    const float* r    = (const float*)d_in[0];
    const float* B_re = (const float*)d_in[1];
    const float* B_im = (const float*)d_in[2];
    const float* C_re = (const float*)d_in[3];
    const float* C_im = (const float*)d_in[4];
    const float* P_re = (const float*)d_in[5];
    const float* P_im = (const float*)d_in[6];
    const float* Q_re = (const float*)d_in[7];
    const float* Q_im = (const float*)d_in[8];
    const float* dre  = (const float*)d_in[9];
    const float* dim_ = (const float*)d_in[10];
    const float* step = (const float*)d_in[11];
    const float* Dp   = (const float*)d_in[12];
    float* out = (float*)d_out;

    static int attr_done = 0;
    if (!attr_done) {
        cudaFuncSetAttribute(k_kf,   cudaFuncAttributeMaxDynamicSharedMemorySize, 2 * BUFSZ * sizeof(float2));
        cudaFuncSetAttribute(k_conv, cudaFuncAttributeMaxDynamicSharedMemorySize, 2 * BUFSZ * sizeof(float2));
        attr_done = 1;
    }

    k_tw<<<5, 256>>>();
    k_prep<<<8, 256>>>(B_re, B_im, P_re, P_im, Q_re, Q_im, dre, dim_, step);
    k_ar<<<dim3(LL / 64, HH / 128), 256>>>(C_re, C_im, B_re, B_im, P_re, P_im);
    k_kf<<<HH, 512, 2 * BUFSZ * sizeof(float2)>>>();
    k_conv<<<dim3(HH / 2, BB), 512, 2 * BUFSZ * sizeof(float2)>>>(r, out, Dp);
}

// round 7
// speedup vs baseline: 2.1984x; 1.1739x over previous
#include <cuda_runtime.h>
#include <math.h>

#define BB 8
#define HH 1024
#define LL 2048
#define NN 64
#define NF 4096
#define PADI(i) ((i) + ((i) >> 4))
#define BUFSZ 4352

__device__ float2 g_cden[LL * NN];
__device__ float2 g_fl[LL];
__device__ float2 g_cl[LL];
__device__ float2 g_ar[(size_t)HH * LL];           // 16 MB
__device__ float2 g_Kf[(size_t)HH * NF];           // 32 MB
__device__ float2 g_tw[1025];
__device__ float2 g_rT[(size_t)BB * 512 * LL];     // 64 MB transposed input
__device__ float2 g_oT[(size_t)BB * 512 * LL];     // 64 MB transposed output

__device__ __forceinline__ float2 cmulf(float2 a, float2 b) {
    return make_float2(fmaf(a.x, b.x, -a.y * b.y), fmaf(a.x, b.y, a.y * b.x));
}
__device__ __forceinline__ void cfma(float2& acc, float2 a, float2 b) {
    acc.x = fmaf(a.x, b.x, fmaf(-a.y, b.y, acc.x));
    acc.y = fmaf(a.x, b.y, fmaf(a.y, b.x, acc.y));
}
__device__ __forceinline__ float2 cadd(float2 a, float2 b) { return make_float2(a.x + b.x, a.y + b.y); }
__device__ __forceinline__ float2 csub(float2 a, float2 b) { return make_float2(a.x - b.x, a.y - b.y); }

template <int DIR>
__device__ __forceinline__ void dft4v(float2 v[4]) {
    float2 apc = cadd(v[0], v[2]), amc = csub(v[0], v[2]);
    float2 bpd = cadd(v[1], v[3]), bmd = csub(v[1], v[3]);
    float2 jb = make_float2(-(float)DIR * bmd.y, (float)DIR * bmd.x);
    v[0] = cadd(apc, bpd); v[1] = cadd(amc, jb);
    v[2] = csub(apc, bpd); v[3] = csub(amc, jb);
}

template <int DIR>
__device__ __forceinline__ void dft8(float2 v[8]) {
    float2 e[4] = {v[0], v[2], v[4], v[6]};
    float2 o[4] = {v[1], v[3], v[5], v[7]};
    dft4v<DIR>(e);
    dft4v<DIR>(o);
    const float R2 = 0.70710678118654752440f;
    float2 w1 = make_float2(R2, (float)DIR * R2);
    float2 w3 = make_float2(-R2, (float)DIR * R2);
    float2 o1 = cmulf(o[1], w1);
    float2 o2 = make_float2(-(float)DIR * o[2].y, (float)DIR * o[2].x);
    float2 o3 = cmulf(o[3], w3);
    v[0] = cadd(e[0], o[0]); v[4] = csub(e[0], o[0]);
    v[1] = cadd(e[1], o1);   v[5] = csub(e[1], o1);
    v[2] = cadd(e[2], o2);   v[6] = csub(e[2], o2);
    v[3] = cadd(e[3], o3);   v[7] = csub(e[3], o3);
}

__device__ __forceinline__ void pass_store(float2* dst, float2 v[8], int ob, int ls, float2 w1) {
    dst[PADI(ob)] = v[0];
    float2 wk = w1;
    dst[PADI(ob + (1 << ls))] = cmulf(v[1], wk);
#pragma unroll
    for (int k = 2; k < 8; k++) {
        wk = cmulf(wk, w1);
        dst[PADI(ob + (k << ls))] = cmulf(v[k], wk);
    }
}

// radix-8 Stockham passes: nn from nn0 down while nn >= nnEnd. Swaps src/dst each pass.
template <int NTOT, int DIR, int NT>
__device__ __forceinline__ void fft_passes(float2*& src, float2*& dst, int nn, int ls, int nnEnd) {
    while (nn >= nnEnd) {
        int tstep = NF / nn;
        for (int idx = threadIdx.x; idx < (NTOT >> 3); idx += NT) {
            int p = idx >> ls;
            int q = idx & ((1 << ls) - 1);
            int base = q + (p << ls);
            float2 v[8];
#pragma unroll
            for (int j = 0; j < 8; j++) v[j] = src[PADI(base + j * (NTOT >> 3))];
            dft8<DIR>(v);
            float2 w1 = __ldg(&g_tw[p * tstep]);
            if (DIR > 0) w1.y = -w1.y;
            pass_store(dst, v, q + (p << (ls + 3)), ls, w1);
        }
        __syncthreads();
        float2* t = src; src = dst; dst = t;
        nn >>= 3;
        ls += 3;
    }
}

// full block FFT (used by k_kf). Result in x for NFFT=2048 and 4096.
template <int NFFT, int DIR, int NT>
__device__ __forceinline__ void block_fft(float2* x, float2* y) {
    float2* src = x;
    float2* dst = y;
    fft_passes<NFFT, DIR, NT>(src, dst, NFFT, 0, 8);
    if (NFFT == LL) {  // radix-4 tail, nn=4, ls=9
        for (int idx = threadIdx.x; idx < (NFFT >> 2); idx += NT) {
            float2 v[4];
#pragma unroll
            for (int j = 0; j < 4; j++) v[j] = src[PADI(idx + j * (NFFT >> 2))];
            dft4v<DIR>(v);
#pragma unroll
            for (int k = 0; k < 4; k++) dst[PADI(idx + (k << 9))] = v[k];
        }
        __syncthreads();
    }
}

__global__ void k_tw() {
    int j = blockIdx.x * blockDim.x + threadIdx.x;
    if (j > 1024) return;
    float ang = -6.28318530717958647692f * (float)j / (float)NF;
    float s, c;
    sincosf(ang, &s, &c);
    g_tw[j] = make_float2(c, s);
}

__global__ void k_prep(const float* __restrict__ B_re, const float* __restrict__ B_im,
                       const float* __restrict__ P_re, const float* __restrict__ P_im,
                       const float* __restrict__ Q_re, const float* __restrict__ Q_im,
                       const float* __restrict__ dre,  const float* __restrict__ dim_,
                       const float* __restrict__ step) {
    int l = blockIdx.x * blockDim.x + threadIdx.x;
    if (l >= LL) return;
    float st = fmaxf(step[0], 1e-6f);
    float ang = (-6.28318530717958647692f * (float)l) / (float)LL;
    float zs, zc;
    sincosf(ang, &zs, &zc);
    float2 omz = make_float2(1.0f - zc, -zs);
    float2 opz = make_float2(1.0f + zc, zs);
    float invp = 1.0f / (opz.x * opz.x + opz.y * opz.y);
    float2 q = cmulf(omz, make_float2(opz.x, -opz.y));
    float2 g = make_float2((2.0f / st) * q.x * invp, (2.0f / st) * q.y * invp);
    float2 k10 = make_float2(0.f, 0.f), k11 = make_float2(0.f, 0.f);
    for (int n = 0; n < NN; n++) {
        float2 den = make_float2(g.x - dre[n], g.y - dim_[n]);
        float di = 1.0f / (den.x * den.x + den.y * den.y);
        float2 cd = make_float2(den.x * di, -den.y * di);
        g_cden[(size_t)l * NN + n] = cd;
        float2 Bv = make_float2(B_re[n], B_im[n]);
        float2 Pv = make_float2(P_re[n], P_im[n]);
        float2 Qv = make_float2(Q_re[n], Q_im[n]);
        cfma(k10, cmulf(Qv, Bv), cd);
        cfma(k11, cmulf(Qv, Pv), cd);
    }
    float2 onep = make_float2(1.0f + k11.x, k11.y);
    float i2 = 1.0f / (onep.x * onep.x + onep.y * onep.y);
    float2 c = cmulf(k10, make_float2(onep.x * i2, -onep.y * i2));
    g_fl[l] = make_float2(2.0f * opz.x * invp, -2.0f * opz.y * invp);
    g_cl[l] = c;
}

__global__ void __launch_bounds__(256) k_ar(const float* __restrict__ C_re, const float* __restrict__ C_im,
                                            const float* __restrict__ B_re, const float* __restrict__ B_im,
                                            const float* __restrict__ P_re, const float* __restrict__ P_im) {
    __shared__ float2 sCD[64 * 65];
    __shared__ float2 sCB[8 * 65];
    __shared__ float2 sCP[8 * 65];
    int l0 = blockIdx.x * 64;
    int tid = threadIdx.x;
    for (int i = tid; i < 64 * 64; i += 256) {
        int ll = i >> 6, n = i & 63;
        sCD[ll * 65 + n] = g_cden[(size_t)(l0 + ll) * NN + n];
    }
    int th = tid >> 5;
    int tl = tid & 31;
    for (int hc = 0; hc < 16; hc++) {
        int hb = blockIdx.y * 128 + hc * 8;
        __syncthreads();
        for (int i = tid; i < 8 * 64; i += 256) {
            int hh = i >> 6, n = i & 63;
            float2 Cv = make_float2(C_re[(size_t)(hb + hh) * NN + n], C_im[(size_t)(hb + hh) * NN + n]);
            sCB[hh * 65 + n] = cmulf(Cv, make_float2(B_re[n], B_im[n]));
            sCP[hh * 65 + n] = cmulf(Cv, make_float2(P_re[n], P_im[n]));
        }
        __syncthreads();
        float2 a00a = make_float2(0.f, 0.f), a01a = make_float2(0.f, 0.f);
        float2 a00b = make_float2(0.f, 0.f), a01b = make_float2(0.f, 0.f);
#pragma unroll
        for (int n = 0; n < 64; n++) {
            float2 cb = sCB[th * 65 + n];
            float2 cp = sCP[th * 65 + n];
            float2 c0 = sCD[tl * 65 + n];
            float2 c1 = sCD[(tl + 32) * 65 + n];
            cfma(a00a, cb, c0); cfma(a01a, cp, c0);
            cfma(a00b, cb, c1); cfma(a01b, cp, c1);
        }
        int h = hb + th;
        int la = l0 + tl, lb = la + 32;
        float2 fa = g_fl[la], ca = g_cl[la];
        float2 fb = g_fl[lb], cb2 = g_cl[lb];
        g_ar[(size_t)h * LL + la] = cmulf(fa, csub(a00a, cmulf(ca, a01a)));
        g_ar[(size_t)h * LL + lb] = cmulf(fb, csub(a00b, cmulf(cb2, a01b)));
    }
}

__global__ void __launch_bounds__(512, 2) k_kf() {
    extern __shared__ float2 sh2[];
    float2* A = sh2;
    float2* Bb = sh2 + BUFSZ;
    int h = blockIdx.x;
    for (int l = threadIdx.x; l < LL; l += 512) A[PADI(l)] = g_ar[(size_t)h * LL + l];
    __syncthreads();
    block_fft<LL, 1, 512>(A, Bb);
    float kv[4];
#pragma unroll
    for (int i = 0; i < 4; i++) {
        int l = threadIdx.x + i * 512;
        kv[i] = A[PADI(l)].x * (1.0f / (float)LL);
    }
    __syncthreads();
#pragma unroll
    for (int i = 0; i < 4; i++) {
        int l = threadIdx.x + i * 512;
        A[PADI(l)] = make_float2(kv[i], 0.f);
        A[PADI(l + LL)] = make_float2(0.f, 0.f);
    }
    __syncthreads();
    block_fft<NF, -1, 512>(A, Bb);
    for (int k = threadIdx.x; k < NF; k += 512) g_Kf[(size_t)h * NF + k] = A[PADI(k)];
}

// transpose r (B,L,H) -> g_rT (B, 512 pairs, L)
__global__ void __launch_bounds__(256) k_tri(const float* __restrict__ r) {
    __shared__ float2 s[32][33];
    int b = blockIdx.z, l0 = blockIdx.x * 32, hp0 = blockIdx.y * 32;
    const float2* r2 = (const float2*)(r + (size_t)b * LL * HH);
    int lane = threadIdx.x & 31, row = threadIdx.x >> 5;
#pragma unroll
    for (int k = 0; k < 4; k++) {
        int rr = row + 8 * k;
        s[rr][lane] = r2[(size_t)(l0 + rr) * 512 + hp0 + lane];
    }
    __syncthreads();
    float2* dst = g_rT + (size_t)b * 512 * LL;
#pragma unroll
    for (int k = 0; k < 4; k++) {
        int rr = row + 8 * k;
        dst[(size_t)(hp0 + rr) * LL + l0 + lane] = s[lane][rr];
    }
}

// transpose g_oT (B, 512 pairs, L) -> out (B,L,H)
__global__ void __launch_bounds__(256) k_tro(float* __restrict__ out) {
    __shared__ float2 s[32][33];
    int b = blockIdx.z, l0 = blockIdx.x * 32, hp0 = blockIdx.y * 32;
    const float2* src = g_oT + (size_t)b * 512 * LL;
    int lane = threadIdx.x & 31, row = threadIdx.x >> 5;
#pragma unroll
    for (int k = 0; k < 4; k++) {
        int rr = row + 8 * k;
        s[rr][lane] = src[(size_t)(hp0 + rr) * LL + l0 + lane];
    }
    __syncthreads();
    float2* o2 = (float2*)(out + (size_t)b * LL * HH);
#pragma unroll
    for (int k = 0; k < 4; k++) {
        int rr = row + 8 * k;
        o2[(size_t)(l0 + rr) * 512 + hp0 + lane] = s[lane][rr];
    }
}

// FFT convolution, 2 channels/CTA, coalesced I/O via g_rT/g_oT, fused boundary passes
__global__ void __launch_bounds__(512, 2) k_conv(const float* __restrict__ Dp) {
    extern __shared__ float2 sh2[];
    float2* A = sh2;
    float2* Bb = sh2 + BUFSZ;
    int hp = blockIdx.x;
    int b = blockIdx.y;
    int tid = threadIdx.x;
    float Dv = Dp[0];
    const float2* rp = g_rT + ((size_t)b * 512 + hp) * LL;
    float2 rv[4];
    float2 v[8];
#pragma unroll
    for (int j = 0; j < 4; j++) {
        rv[j] = rp[tid + j * 512];
        v[j] = rv[j];
        v[j + 4] = make_float2(0.f, 0.f);
    }
    // fused forward pass 1 (nn=4096, ls=0, p=tid)
    dft8<-1>(v);
    pass_store(A, v, tid << 3, 0, __ldg(&g_tw[tid]));
    __syncthreads();
    float2* src = A;
    float2* dst = Bb;
    fft_passes<NF, -1, 512>(src, dst, 512, 3, 8);   // passes 512,64,8 -> data in src
    // untangle + per-channel multiply (spectra of the two packed real channels)
    {
        const float2* K0 = g_Kf + (size_t)(2 * hp) * NF;
        const float2* K1 = K0 + NF;
        float2* W = src;
        for (int k = tid; k <= NF / 2; k += 512) {
            int km = (NF - k) & (NF - 1);
            float2 a = W[PADI(k)];
            float2 bc = W[PADI(km)]; bc.y = -bc.y;
            float2 X0 = make_float2(0.5f * (a.x + bc.x), 0.5f * (a.y + bc.y));
            float2 dd = make_float2(0.5f * (a.x - bc.x), 0.5f * (a.y - bc.y));
            float2 X1 = make_float2(dd.y, -dd.x);
            float2 t0 = cmulf(X0, __ldg(&K0[k]));
            float2 t1 = cmulf(X1, __ldg(&K1[k]));
            W[PADI(k)]  = make_float2(t0.x - t1.y, t0.y + t1.x);
            W[PADI(km)] = make_float2(t0.x + t1.y, -t0.y + t1.x);
        }
    }
    __syncthreads();
    fft_passes<NF, 1, 512>(src, dst, NF, 0, 64);    // passes 4096,512,64 -> data in src
    // fused inverse final pass (nn=8, ls=9, p=0, w=1) + epilogue
#pragma unroll
    for (int j = 0; j < 8; j++) v[j] = src[PADI(tid + j * 512)];
    dft8<1>(v);
    float2* op = g_oT + ((size_t)b * 512 + hp) * LL;
#pragma unroll
    for (int k = 0; k < 4; k++) {
        float y0 = fmaf(Dv, rv[k].x, v[k].x * (1.0f / (float)NF));
        float y1 = fmaf(Dv, rv[k].y, v[k].y * (1.0f / (float)NF));
        float g0 = 0.5f * y0 * (1.0f + erff(y0 * 0.70710678118654752f));
        float g1 = 0.5f * y1 * (1.0f + erff(y1 * 0.70710678118654752f));
        op[tid + k * 512] = make_float2(g0, g1);
    }
}

extern "C" void kernel_launch(void* const* d_in, const int* in_sizes, int n_in,
                              void* d_out, int out_size) {
    const float* r    = (const float*)d_in[0];
    const float* B_re = (const float*)d_in[1];
    const float* B_im = (const float*)d_in[2];
    const float* C_re = (const float*)d_in[3];
    const float* C_im = (const float*)d_in[4];
    const float* P_re = (const float*)d_in[5];
    const float* P_im = (const float*)d_in[6];
    const float* Q_re = (const float*)d_in[7];
    const float* Q_im = (const float*)d_in[8];
    const float* dre  = (const float*)d_in[9];
    const float* dim_ = (const float*)d_in[10];
    const float* step = (const float*)d_in[11];
    const float* Dp   = (const float*)d_in[12];
    float* out = (float*)d_out;

    static int attr_done = 0;
    if (!attr_done) {
        cudaFuncSetAttribute(k_kf,   cudaFuncAttributeMaxDynamicSharedMemorySize, 2 * BUFSZ * sizeof(float2));
        cudaFuncSetAttribute(k_conv, cudaFuncAttributeMaxDynamicSharedMemorySize, 2 * BUFSZ * sizeof(float2));
        attr_done = 1;
    }

    k_tw<<<5, 256>>>();
    k_prep<<<8, 256>>>(B_re, B_im, P_re, P_im, Q_re, Q_im, dre, dim_, step);
    k_tri<<<dim3(LL / 32, 16, BB), 256>>>(r);
    k_ar<<<dim3(LL / 64, HH / 128), 256>>>(C_re, C_im, B_re, B_im, P_re, P_im);
    k_kf<<<HH, 512, 2 * BUFSZ * sizeof(float2)>>>();
    k_conv<<<dim3(HH / 2, BB), 512, 2 * BUFSZ * sizeof(float2)>>>(Dp);
    k_tro<<<dim3(LL / 32, 16, BB), 256>>>(out);
}

// round 8
// speedup vs baseline: 2.2842x; 1.0391x over previous
#include <cuda_runtime.h>
#include <math.h>

#define BB 8
#define HH 1024
#define LL 2048
#define NN 64
#define NF 4096
#define PADI(i) ((i) + ((i) >> 4))
#define BUFSZ 4352

__device__ float2 g_cden[LL * NN];
__device__ float2 g_fl[LL];
__device__ float2 g_cl[LL];
__device__ float2 g_ar[(size_t)HH * LL];           // 16 MB
__device__ float2 g_Kf[(size_t)HH * NF];           // 32 MB
__device__ float2 g_tw[1025];
__device__ float2 g_rT[(size_t)BB * 512 * LL];     // 64 MB transposed input
__device__ float2 g_oT[(size_t)BB * 512 * LL];     // 64 MB transposed output

__device__ __forceinline__ float2 cmulf(float2 a, float2 b) {
    return make_float2(fmaf(a.x, b.x, -a.y * b.y), fmaf(a.x, b.y, a.y * b.x));
}
__device__ __forceinline__ void cfma(float2& acc, float2 a, float2 b) {
    acc.x = fmaf(a.x, b.x, fmaf(-a.y, b.y, acc.x));
    acc.y = fmaf(a.x, b.y, fmaf(a.y, b.x, acc.y));
}
__device__ __forceinline__ float2 cadd(float2 a, float2 b) { return make_float2(a.x + b.x, a.y + b.y); }
__device__ __forceinline__ float2 csub(float2 a, float2 b) { return make_float2(a.x - b.x, a.y - b.y); }

template <int DIR>
__device__ __forceinline__ void dft4v(float2 v[4]) {
    float2 apc = cadd(v[0], v[2]), amc = csub(v[0], v[2]);
    float2 bpd = cadd(v[1], v[3]), bmd = csub(v[1], v[3]);
    float2 jb = make_float2(-(float)DIR * bmd.y, (float)DIR * bmd.x);
    v[0] = cadd(apc, bpd); v[1] = cadd(amc, jb);
    v[2] = csub(apc, bpd); v[3] = csub(amc, jb);
}

template <int DIR>
__device__ __forceinline__ void dft8(float2 v[8]) {
    float2 e[4] = {v[0], v[2], v[4], v[6]};
    float2 o[4] = {v[1], v[3], v[5], v[7]};
    dft4v<DIR>(e);
    dft4v<DIR>(o);
    const float R2 = 0.70710678118654752440f;
    float2 w1 = make_float2(R2, (float)DIR * R2);
    float2 w3 = make_float2(-R2, (float)DIR * R2);
    float2 o1 = cmulf(o[1], w1);
    float2 o2 = make_float2(-(float)DIR * o[2].y, (float)DIR * o[2].x);
    float2 o3 = cmulf(o[3], w3);
    v[0] = cadd(e[0], o[0]); v[4] = csub(e[0], o[0]);
    v[1] = cadd(e[1], o1);   v[5] = csub(e[1], o1);
    v[2] = cadd(e[2], o2);   v[6] = csub(e[2], o2);
    v[3] = cadd(e[3], o3);   v[7] = csub(e[3], o3);
}

__device__ __forceinline__ void pass_store(float2* dst, float2 v[8], int ob, int ls, float2 w1) {
    dst[PADI(ob)] = v[0];
    float2 wk = w1;
    dst[PADI(ob + (1 << ls))] = cmulf(v[1], wk);
#pragma unroll
    for (int k = 2; k < 8; k++) {
        wk = cmulf(wk, w1);
        dst[PADI(ob + (k << ls))] = cmulf(v[k], wk);
    }
}

template <int NTOT, int DIR, int NT>
__device__ __forceinline__ void fft_passes(float2*& src, float2*& dst, int nn, int ls, int nnEnd) {
    while (nn >= nnEnd) {
        int tstep = NF / nn;
        for (int idx = threadIdx.x; idx < (NTOT >> 3); idx += NT) {
            int p = idx >> ls;
            int q = idx & ((1 << ls) - 1);
            int base = q + (p << ls);
            float2 v[8];
#pragma unroll
            for (int j = 0; j < 8; j++) v[j] = src[PADI(base + j * (NTOT >> 3))];
            dft8<DIR>(v);
            float2 w1 = __ldg(&g_tw[p * tstep]);
            if (DIR > 0) w1.y = -w1.y;
            pass_store(dst, v, q + (p << (ls + 3)), ls, w1);
        }
        __syncthreads();
        float2* t = src; src = dst; dst = t;
        nn >>= 3;
        ls += 3;
    }
}

template <int NFFT, int DIR, int NT>
__device__ __forceinline__ void block_fft(float2* x, float2* y) {
    float2* src = x;
    float2* dst = y;
    fft_passes<NFFT, DIR, NT>(src, dst, NFFT, 0, 8);
    if (NFFT == LL) {  // radix-4 tail, nn=4, ls=9
        for (int idx = threadIdx.x; idx < (NFFT >> 2); idx += NT) {
            float2 v[4];
#pragma unroll
            for (int j = 0; j < 4; j++) v[j] = src[PADI(idx + j * (NFFT >> 2))];
            dft4v<DIR>(v);
#pragma unroll
            for (int k = 0; k < 4; k++) dst[PADI(idx + (k << 9))] = v[k];
        }
        __syncthreads();
    }
}

__global__ void k_tw() {
    int j = blockIdx.x * blockDim.x + threadIdx.x;
    if (j > 1024) return;
    float ang = -6.28318530717958647692f * (float)j / (float)NF;
    float s, c;
    sincosf(ang, &s, &c);
    g_tw[j] = make_float2(c, s);
}

__global__ void k_prep(const float* __restrict__ B_re, const float* __restrict__ B_im,
                       const float* __restrict__ P_re, const float* __restrict__ P_im,
                       const float* __restrict__ Q_re, const float* __restrict__ Q_im,
                       const float* __restrict__ dre,  const float* __restrict__ dim_,
                       const float* __restrict__ step) {
    int l = blockIdx.x * blockDim.x + threadIdx.x;
    if (l >= LL) return;
    float st = fmaxf(step[0], 1e-6f);
    float ang = (-6.28318530717958647692f * (float)l) / (float)LL;
    float zs, zc;
    sincosf(ang, &zs, &zc);
    float2 omz = make_float2(1.0f - zc, -zs);
    float2 opz = make_float2(1.0f + zc, zs);
    float invp = 1.0f / (opz.x * opz.x + opz.y * opz.y);
    float2 q = cmulf(omz, make_float2(opz.x, -opz.y));
    float2 g = make_float2((2.0f / st) * q.x * invp, (2.0f / st) * q.y * invp);
    float2 k10 = make_float2(0.f, 0.f), k11 = make_float2(0.f, 0.f);
    for (int n = 0; n < NN; n++) {
        float2 den = make_float2(g.x - dre[n], g.y - dim_[n]);
        float di = 1.0f / (den.x * den.x + den.y * den.y);
        float2 cd = make_float2(den.x * di, -den.y * di);
        g_cden[(size_t)l * NN + n] = cd;
        float2 Bv = make_float2(B_re[n], B_im[n]);
        float2 Pv = make_float2(P_re[n], P_im[n]);
        float2 Qv = make_float2(Q_re[n], Q_im[n]);
        cfma(k10, cmulf(Qv, Bv), cd);
        cfma(k11, cmulf(Qv, Pv), cd);
    }
    float2 onep = make_float2(1.0f + k11.x, k11.y);
    float i2 = 1.0f / (onep.x * onep.x + onep.y * onep.y);
    float2 c = cmulf(k10, make_float2(onep.x * i2, -onep.y * i2));
    g_fl[l] = make_float2(2.0f * opz.x * invp, -2.0f * opz.y * invp);
    g_cl[l] = c;
}

// K2: at_roots, 64l x 64h tile, 4x4 register blocking, n staged in chunks of 16
__global__ void __launch_bounds__(256) k_ar(const float* __restrict__ C_re, const float* __restrict__ C_im,
                                            const float* __restrict__ B_re, const float* __restrict__ B_im,
                                            const float* __restrict__ P_re, const float* __restrict__ P_im) {
    __shared__ float2 sCD[64 * 17];
    __shared__ float2 sCB[64 * 17];
    __shared__ float2 sCP[64 * 17];
    int l0 = blockIdx.x * 64;
    int h0 = blockIdx.y * 64;
    int tid = threadIdx.x;
    int tl = (tid & 15) * 4;   // 4 l per thread
    int th = (tid >> 4) * 4;   // 4 h per thread
    float2 a00[4][4], a01[4][4];
#pragma unroll
    for (int ih = 0; ih < 4; ih++)
#pragma unroll
        for (int il = 0; il < 4; il++) { a00[ih][il] = make_float2(0.f, 0.f); a01[ih][il] = make_float2(0.f, 0.f); }

    for (int nc = 0; nc < NN; nc += 16) {
        __syncthreads();
        for (int i = tid; i < 64 * 16; i += 256) {
            int row = i >> 4, n = i & 15;
            int gn = nc + n;
            sCD[row * 17 + n] = g_cden[(size_t)(l0 + row) * NN + gn];
            float2 Cv = make_float2(C_re[(size_t)(h0 + row) * NN + gn], C_im[(size_t)(h0 + row) * NN + gn]);
            sCB[row * 17 + n] = cmulf(Cv, make_float2(B_re[gn], B_im[gn]));
            sCP[row * 17 + n] = cmulf(Cv, make_float2(P_re[gn], P_im[gn]));
        }
        __syncthreads();
#pragma unroll
        for (int n = 0; n < 16; n++) {
            float2 cd[4], cb[4], cp[4];
#pragma unroll
            for (int il = 0; il < 4; il++) cd[il] = sCD[(tl + il) * 17 + n];
#pragma unroll
            for (int ih = 0; ih < 4; ih++) {
                cb[ih] = sCB[(th + ih) * 17 + n];
                cp[ih] = sCP[(th + ih) * 17 + n];
            }
#pragma unroll
            for (int ih = 0; ih < 4; ih++)
#pragma unroll
                for (int il = 0; il < 4; il++) {
                    cfma(a00[ih][il], cb[ih], cd[il]);
                    cfma(a01[ih][il], cp[ih], cd[il]);
                }
        }
    }
    float2 fl[4], cl[4];
#pragma unroll
    for (int il = 0; il < 4; il++) { fl[il] = g_fl[l0 + tl + il]; cl[il] = g_cl[l0 + tl + il]; }
#pragma unroll
    for (int ih = 0; ih < 4; ih++) {
        float2 res[4];
#pragma unroll
        for (int il = 0; il < 4; il++)
            res[il] = cmulf(fl[il], csub(a00[ih][il], cmulf(cl[il], a01[ih][il])));
        float4* dst = (float4*)(g_ar + (size_t)(h0 + th + ih) * LL + l0 + tl);
        dst[0] = make_float4(res[0].x, res[0].y, res[1].x, res[1].y);
        dst[1] = make_float4(res[2].x, res[2].y, res[3].x, res[3].y);
    }
}

__global__ void __launch_bounds__(512, 2) k_kf() {
    extern __shared__ float2 sh2[];
    float2* A = sh2;
    float2* Bb = sh2 + BUFSZ;
    int h = blockIdx.x;
    for (int l = threadIdx.x; l < LL; l += 512) A[PADI(l)] = g_ar[(size_t)h * LL + l];
    __syncthreads();
    block_fft<LL, 1, 512>(A, Bb);
    float kv[4];
#pragma unroll
    for (int i = 0; i < 4; i++) {
        int l = threadIdx.x + i * 512;
        kv[i] = A[PADI(l)].x * (1.0f / (float)LL);
    }
    __syncthreads();
#pragma unroll
    for (int i = 0; i < 4; i++) {
        int l = threadIdx.x + i * 512;
        A[PADI(l)] = make_float2(kv[i], 0.f);
        A[PADI(l + LL)] = make_float2(0.f, 0.f);
    }
    __syncthreads();
    block_fft<NF, -1, 512>(A, Bb);
    for (int k = threadIdx.x; k < NF; k += 512) g_Kf[(size_t)h * NF + k] = A[PADI(k)];
}

__global__ void __launch_bounds__(256) k_tri(const float* __restrict__ r) {
    __shared__ float2 s[32][33];
    int b = blockIdx.z, l0 = blockIdx.x * 32, hp0 = blockIdx.y * 32;
    const float2* r2 = (const float2*)(r + (size_t)b * LL * HH);
    int lane = threadIdx.x & 31, row = threadIdx.x >> 5;
#pragma unroll
    for (int k = 0; k < 4; k++) {
        int rr = row + 8 * k;
        s[rr][lane] = r2[(size_t)(l0 + rr) * 512 + hp0 + lane];
    }
    __syncthreads();
    float2* dst = g_rT + (size_t)b * 512 * LL;
#pragma unroll
    for (int k = 0; k < 4; k++) {
        int rr = row + 8 * k;
        dst[(size_t)(hp0 + rr) * LL + l0 + lane] = s[lane][rr];
    }
}

__global__ void __launch_bounds__(256) k_tro(float* __restrict__ out) {
    __shared__ float2 s[32][33];
    int b = blockIdx.z, l0 = blockIdx.x * 32, hp0 = blockIdx.y * 32;
    const float2* src = g_oT + (size_t)b * 512 * LL;
    int lane = threadIdx.x & 31, row = threadIdx.x >> 5;
#pragma unroll
    for (int k = 0; k < 4; k++) {
        int rr = row + 8 * k;
        s[rr][lane] = src[(size_t)(hp0 + rr) * LL + l0 + lane];
    }
    __syncthreads();
    float2* o2 = (float2*)(out + (size_t)b * LL * HH);
#pragma unroll
    for (int k = 0; k < 4; k++) {
        int rr = row + 8 * k;
        o2[(size_t)(l0 + rr) * 512 + hp0 + lane] = s[lane][rr];
    }
}

__global__ void __launch_bounds__(512, 2) k_conv(const float* __restrict__ Dp) {
    extern __shared__ float2 sh2[];
    float2* A = sh2;
    float2* Bb = sh2 + BUFSZ;
    int hp = blockIdx.x;
    int b = blockIdx.y;
    int tid = threadIdx.x;
    float Dv = Dp[0];
    const float2* rp = g_rT + ((size_t)b * 512 + hp) * LL;
    float2 rv[4];
    float2 v[8];
#pragma unroll
    for (int j = 0; j < 4; j++) {
        rv[j] = rp[tid + j * 512];
        v[j] = rv[j];
        v[j + 4] = make_float2(0.f, 0.f);
    }
    dft8<-1>(v);
    pass_store(A, v, tid << 3, 0, __ldg(&g_tw[tid]));
    __syncthreads();
    float2* src = A;
    float2* dst = Bb;
    fft_passes<NF, -1, 512>(src, dst, 512, 3, 8);
    {
        const float2* K0 = g_Kf + (size_t)(2 * hp) * NF;
        const float2* K1 = K0 + NF;
        float2* W = src;
        for (int k = tid; k <= NF / 2; k += 512) {
            int km = (NF - k) & (NF - 1);
            float2 a = W[PADI(k)];
            float2 bc = W[PADI(km)]; bc.y = -bc.y;
            float2 X0 = make_float2(0.5f * (a.x + bc.x), 0.5f * (a.y + bc.y));
            float2 dd = make_float2(0.5f * (a.x - bc.x), 0.5f * (a.y - bc.y));
            float2 X1 = make_float2(dd.y, -dd.x);
            float2 t0 = cmulf(X0, __ldg(&K0[k]));
            float2 t1 = cmulf(X1, __ldg(&K1[k]));
            W[PADI(k)]  = make_float2(t0.x - t1.y, t0.y + t1.x);
            W[PADI(km)] = make_float2(t0.x + t1.y, -t0.y + t1.x);
        }
    }
    __syncthreads();
    fft_passes<NF, 1, 512>(src, dst, NF, 0, 64);
#pragma unroll
    for (int j = 0; j < 8; j++) v[j] = src[PADI(tid + j * 512)];
    dft8<1>(v);
    float2* op = g_oT + ((size_t)b * 512 + hp) * LL;
#pragma unroll
    for (int k = 0; k < 4; k++) {
        float y0 = fmaf(Dv, rv[k].x, v[k].x * (1.0f / (float)NF));
        float y1 = fmaf(Dv, rv[k].y, v[k].y * (1.0f / (float)NF));
        float g0 = 0.5f * y0 * (1.0f + erff(y0 * 0.70710678118654752f));
        float g1 = 0.5f * y1 * (1.0f + erff(y1 * 0.70710678118654752f));
        op[tid + k * 512] = make_float2(g0, g1);
    }
}

extern "C" void kernel_launch(void* const* d_in, const int* in_sizes, int n_in,
                              void* d_out, int out_size) {
    const float* r    = (const float*)d_in[0];
    const float* B_re = (const float*)d_in[1];
    const float* B_im = (const float*)d_in[2];
    const float* C_re = (const float*)d_in[3];
    const float* C_im = (const float*)d_in[4];
    const float* P_re = (const float*)d_in[5];
    const float* P_im = (const float*)d_in[6];
    const float* Q_re = (const float*)d_in[7];
    const float* Q_im = (const float*)d_in[8];
    const float* dre  = (const float*)d_in[9];
    const float* dim_ = (const float*)d_in[10];
    const float* step = (const float*)d_in[11];
    const float* Dp   = (const float*)d_in[12];
    float* out = (float*)d_out;

    static int attr_done = 0;
    if (!attr_done) {
        cudaFuncSetAttribute(k_kf,   cudaFuncAttributeMaxDynamicSharedMemorySize, 2 * BUFSZ * sizeof(float2));
        cudaFuncSetAttribute(k_conv, cudaFuncAttributeMaxDynamicSharedMemorySize, 2 * BUFSZ * sizeof(float2));
        attr_done = 1;
    }

    k_tw<<<5, 256>>>();
    k_prep<<<8, 256>>>(B_re, B_im, P_re, P_im, Q_re, Q_im, dre, dim_, step);
    k_tri<<<dim3(LL / 32, 16, BB), 256>>>(r);
    k_ar<<<dim3(LL / 64, HH / 64), 256>>>(C_re, C_im, B_re, B_im, P_re, P_im);
    k_kf<<<HH, 512, 2 * BUFSZ * sizeof(float2)>>>();
    k_conv<<<dim3(HH / 2, BB), 512, 2 * BUFSZ * sizeof(float2)>>>(Dp);
    k_tro<<<dim3(LL / 32, 16, BB), 256>>>(out);
}